// round 1
// baseline (speedup 1.0000x reference)
#include <cuda_runtime.h>
#include <math.h>

// Problem constants
#define BB 16
#define CC 256
#define LL 2048
#define EE 512
#define NN 64
#define HH 512
#define H2 1024

// ---------------- scratch (device globals; no allocation allowed) ----------------
__device__ float  g_d[BB * CC];                 // diffusion projection [B,C]
__device__ float2 g_z [2 * HH * NN];            // per-layer discrete poles z = exp(dt*A)
__device__ float2 g_ct[2 * HH * NN];            // per-layer 2*Ct (ZOH C, factor 2 folded)
__device__ float  g_u[BB * HH * LL];            // [B,H,L] activation buffer
__device__ float  g_y[BB * HH * LL];            // [B,H,L] activation buffer
__device__ float  g_t[(size_t)BB * H2 * LL];    // [B,2H,L] GEMM output buffer

// ---------------- math helpers ----------------
__device__ __forceinline__ float sigf(float x) {
    return 1.f / (1.f + __expf(-x));
}
__device__ __forceinline__ float tanh_fast(float x) {
    float ax = fabsf(x);
    float e = __expf(-2.f * ax);
    float t = (1.f - e) / (1.f + e);
    return copysignf(t, x);
}
__device__ __forceinline__ float geluf(float x) {
    // tanh-approx GELU (JAX default approximate=True)
    float x3 = x * x * x;
    return 0.5f * x * (1.f + tanh_fast(0.7978845608028654f * fmaf(0.044715f, x3, x)));
}

// ---------------- diffusion embedding projection: d[b,c] ----------------
__global__ void k_dproj(const float* __restrict__ demb, const float* __restrict__ W,
                        const float* __restrict__ bias, float* __restrict__ d) {
    int b = blockIdx.x;
    int c = threadIdx.x;  // 256 threads
    __shared__ float se[EE];
    for (int e = threadIdx.x; e < EE; e += 256) se[e] = demb[b * EE + e];
    __syncthreads();
    float acc = 0.f;
#pragma unroll 8
    for (int e = 0; e < EE; e++) acc = fmaf(se[e], W[c * EE + e], acc);
    d[b * CC + c] = acc + bias[c];
}

// ---------------- SSM precompute: z = exp(dt*A), ct = 2*C*(z-1)/A ----------------
__global__ void k_prec(const float* __restrict__ log_dt, const float* __restrict__ Are,
                       const float* __restrict__ Aim, const float* __restrict__ Cre,
                       const float* __restrict__ Cim, float2* __restrict__ z,
                       float2* __restrict__ ct) {
    int i = blockIdx.x * blockDim.x + threadIdx.x;
    if (i >= HH * NN) return;
    int h = i / NN;
    float dt = expf(log_dt[h]);
    float A_r = Are[i], A_i = Aim[i];
    float ar = A_r * dt, ai = A_i * dt;
    float er = expf(ar);
    float s, c0;
    sincosf(ai, &s, &c0);
    float zr = er * c0, zi = er * s;
    float wr = zr - 1.f, wi = zi;
    float den = A_r * A_r + A_i * A_i;
    float inv = 1.f / den;
    float qr = (wr * A_r + wi * A_i) * inv;
    float qi = (wi * A_r - wr * A_i) * inv;
    float cr = Cre[i], ci = Cim[i];
    ct[i] = make_float2(2.f * (cr * qr - ci * qi), 2.f * (cr * qi + ci * qr));
    z[i] = make_float2(zr, zi);
}

// ---------------- diagonal SSM recurrence + D-skip + GELU ----------------
// One warp per (b,h) sequence; 64 complex states = 2 per lane.
__global__ void k_ssm(const float* __restrict__ in, float* __restrict__ out,
                      const float2* __restrict__ zarr, const float2* __restrict__ ctarr,
                      const float* __restrict__ Dv) {
    int w = (blockIdx.x * blockDim.x + threadIdx.x) >> 5;
    int lane = threadIdx.x & 31;
    int b = w / HH, h = w - b * HH;
    float2 z0 = zarr[h * NN + lane];
    float2 z1 = zarr[h * NN + 32 + lane];
    float2 c0 = ctarr[h * NN + lane];
    float2 c1 = ctarr[h * NN + 32 + lane];
    float Dh = Dv[h];
    const float4* ip = (const float4*)(in + (size_t)(b * HH + h) * LL);
    float4* op = (float4*)(out + (size_t)(b * HH + h) * LL);
    float s0r = 0.f, s0i = 0.f, s1r = 0.f, s1i = 0.f;
    for (int l4 = 0; l4 < LL / 4; l4++) {
        float4 u4 = __ldg(ip + l4);
        float o[4];
#pragma unroll
        for (int j = 0; j < 4; j++) {
            float u = (j == 0) ? u4.x : (j == 1) ? u4.y : (j == 2) ? u4.z : u4.w;
            float sr = s0r, si = s0i;
            s0r = fmaf(z0.x, sr, fmaf(-z0.y, si, u));
            s0i = fmaf(z0.x, si, z0.y * sr);
            sr = s1r; si = s1i;
            s1r = fmaf(z1.x, sr, fmaf(-z1.y, si, u));
            s1i = fmaf(z1.x, si, z1.y * sr);
            float p = c0.x * s0r;
            p = fmaf(-c0.y, s0i, p);
            p = fmaf(c1.x, s1r, p);
            p = fmaf(-c1.y, s1i, p);
#pragma unroll
            for (int off = 16; off; off >>= 1) p += __shfl_xor_sync(0xffffffffu, p, off);
            float yv = fmaf(Dh, u, p);
            o[j] = geluf(yv);
        }
        if (lane == 0) op[l4] = make_float4(o[0], o[1], o[2], o[3]);
    }
}

// ---------------- tiled fp32 GEMM: Y[b,o,l] = sum_k W[o,k]*(X[b,k,l]+addv[b,k]) + bias[o] ----------------
__global__ void k_gemm(const float* __restrict__ W, const float* __restrict__ X,
                       const float* __restrict__ bias, float* __restrict__ Y,
                       int O, int K, const float* __restrict__ addv) {
    __shared__ float sA[16][64];      // [k][o]
    __shared__ float sB[16][68];      // [k][l], padded
    int t = threadIdx.x;              // 256 threads
    int tx = t & 15, ty = t >> 4;
    int o0 = blockIdx.y * 64, l0 = blockIdx.x * 64;
    const float* Xb = X + (size_t)blockIdx.z * K * LL;
    float acc[4][4] = {{0.f}};
    for (int kc = 0; kc < K; kc += 16) {
        {
            int row = t >> 2, seg = t & 3;
            float4 wv = *(const float4*)(W + (size_t)(o0 + row) * K + kc + seg * 4);
            sA[seg * 4 + 0][row] = wv.x;
            sA[seg * 4 + 1][row] = wv.y;
            sA[seg * 4 + 2][row] = wv.z;
            sA[seg * 4 + 3][row] = wv.w;
        }
        {
            int xr = t >> 4, xs = t & 15;
            float4 xv = *(const float4*)(Xb + (size_t)(kc + xr) * LL + l0 + xs * 4);
            if (addv) {
                float a = __ldg(addv + blockIdx.z * K + kc + xr);
                xv.x += a; xv.y += a; xv.z += a; xv.w += a;
            }
            *(float4*)(&sB[xr][xs * 4]) = xv;
        }
        __syncthreads();
#pragma unroll
        for (int k = 0; k < 16; k++) {
            float4 av = *(const float4*)(&sA[k][ty * 4]);
            float4 bv = *(const float4*)(&sB[k][tx * 4]);
            float a4[4] = {av.x, av.y, av.z, av.w};
            float b4[4] = {bv.x, bv.y, bv.z, bv.w};
#pragma unroll
            for (int i = 0; i < 4; i++)
#pragma unroll
                for (int j = 0; j < 4; j++) acc[i][j] = fmaf(a4[i], b4[j], acc[i][j]);
        }
        __syncthreads();
    }
#pragma unroll
    for (int i = 0; i < 4; i++) {
        float bi = bias[o0 + ty * 4 + i];
        float* yp = Y + (size_t)blockIdx.z * O * LL + (size_t)(o0 + ty * 4 + i) * LL + l0 + tx * 4;
        float4 v = make_float4(acc[i][0] + bi, acc[i][1] + bi, acc[i][2] + bi, acc[i][3] + bi);
        *(float4*)yp = v;
    }
}

// ---------------- GLU: u[b,h,l] = t[b,h,l] * sigmoid(t[b,h+H,l]) ----------------
__global__ void k_glu(const float* __restrict__ t, float* __restrict__ u) {
    int i = blockIdx.x * 256 + threadIdx.x;  // over B*H*L
    int b = i / (HH * LL);
    int r = i - b * HH * LL;
    const float* tb = t + (size_t)b * H2 * LL;
    float a = tb[r];
    float g = tb[r + HH * LL];
    u[i] = a * sigf(g);
}

// ---------------- LayerNorm over channel dim (in-place on [B,H,L]) ----------------
__global__ void k_ln(float* __restrict__ u, const float* __restrict__ g,
                     const float* __restrict__ be) {
    int i = blockIdx.x * blockDim.x + threadIdx.x;  // over B*L
    int b = i / LL, l = i - b * LL;
    float* base = u + (size_t)b * HH * LL + l;
    float sum = 0.f, ss = 0.f;
#pragma unroll 8
    for (int h = 0; h < HH; h++) {
        float v = base[(size_t)h * LL];
        sum += v;
        ss = fmaf(v, v, ss);
    }
    float mu = sum * (1.f / HH);
    float var = ss * (1.f / HH) - mu * mu;
    float rs = rsqrtf(var + 1e-5f);
#pragma unroll 8
    for (int h = 0; h < HH; h++) {
        float v = base[(size_t)h * LL];
        base[(size_t)h * LL] = (v - mu) * rs * __ldg(g + h) + __ldg(be + h);
    }
}

// ---------------- gate/filter activation: z = sigmoid(u[:, :C]) * tanh(u[:, C:]) ----------------
__global__ void k_act(const float* __restrict__ u, float* __restrict__ zout) {
    int i = blockIdx.x * 256 + threadIdx.x;  // over B*C*L
    int b = i / (CC * LL);
    int r = i - b * CC * LL;
    const float* ub = u + (size_t)b * HH * LL;
    float gt = ub[r];
    float fl = ub[r + CC * LL];
    zout[i] = sigf(gt) * tanh_fast(fl);
}

// ---------------- final: residual = (x + t[:, :C])/sqrt(2), skip = t[:, C:] ----------------
__global__ void k_final(const float* __restrict__ t, const float* __restrict__ x,
                        float* __restrict__ out) {
    int i = blockIdx.x * 256 + threadIdx.x;  // over B*C*L
    int b = i / (CC * LL);
    int r = i - b * CC * LL;
    const float* tb = t + (size_t)b * HH * LL;
    out[i] = (x[i] + tb[r]) * 0.70710678118654752f;
    out[BB * CC * LL + i] = tb[r + CC * LL];
}

// ---------------- launch ----------------
extern "C" void kernel_launch(void* const* d_in, const int* in_sizes, int n_in,
                              void* d_out, int out_size) {
    const float* x    = (const float*)d_in[0];
    const float* demb = (const float*)d_in[1];
    const float* dpW  = (const float*)d_in[2];
    const float* dpb  = (const float*)d_in[3];
    const float* inW  = (const float*)d_in[4];
    const float* inb  = (const float*)d_in[5];
    const float* outW = (const float*)d_in[6];
    const float* outb = (const float*)d_in[7];
    const float* ln1g = (const float*)d_in[8];
    const float* ln1b = (const float*)d_in[9];
    const float* ln2g = (const float*)d_in[10];
    const float* ln2b = (const float*)d_in[11];
    // s41_: log_dt, A_re, A_im, C_re, C_im, D, oW, ob  (12..19)
    // s42_: same (20..27)
    const float* s1_logdt = (const float*)d_in[12];
    const float* s1_Are   = (const float*)d_in[13];
    const float* s1_Aim   = (const float*)d_in[14];
    const float* s1_Cre   = (const float*)d_in[15];
    const float* s1_Cim   = (const float*)d_in[16];
    const float* s1_D     = (const float*)d_in[17];
    const float* s1_oW    = (const float*)d_in[18];
    const float* s1_ob    = (const float*)d_in[19];
    const float* s2_logdt = (const float*)d_in[20];
    const float* s2_Are   = (const float*)d_in[21];
    const float* s2_Aim   = (const float*)d_in[22];
    const float* s2_Cre   = (const float*)d_in[23];
    const float* s2_Cim   = (const float*)d_in[24];
    const float* s2_D     = (const float*)d_in[25];
    const float* s2_oW    = (const float*)d_in[26];
    const float* s2_ob    = (const float*)d_in[27];

    float* out = (float*)d_out;

    float *du, *dy, *dt, *dd;
    float2 *dz, *dct;
    cudaGetSymbolAddress((void**)&du, g_u);
    cudaGetSymbolAddress((void**)&dy, g_y);
    cudaGetSymbolAddress((void**)&dt, g_t);
    cudaGetSymbolAddress((void**)&dd, g_d);
    cudaGetSymbolAddress((void**)&dz, g_z);
    cudaGetSymbolAddress((void**)&dct, g_ct);

    const int HN = HH * NN;

    // 1. diffusion projection
    k_dproj<<<BB, 256>>>(demb, dpW, dpb, dd);
    // 2. SSM precompute (both layers)
    k_prec<<<(HN + 255) / 256, 256>>>(s1_logdt, s1_Are, s1_Aim, s1_Cre, s1_Cim, dz, dct);
    k_prec<<<(HN + 255) / 256, 256>>>(s2_logdt, s2_Are, s2_Aim, s2_Cre, s2_Cim, dz + HN, dct + HN);
    // 3. input projection: u = in_W @ (x + d) + in_b    [B,H,L]
    k_gemm<<<dim3(LL / 64, HH / 64, BB), 256>>>(inW, x, inb, du, HH, CC, dd);
    // 4. S4 layer 1: recurrence + D skip + GELU -> y
    k_ssm<<<(BB * HH) / 4, 128>>>(du, dy, dz, dct, s1_D);
    // 5. output linear of S4_1: t = oW1 @ y + ob1   [B,2H,L]
    k_gemm<<<dim3(LL / 64, H2 / 64, BB), 256>>>(s1_oW, dy, s1_ob, dt, H2, HH, nullptr);
    // 6. GLU -> u; LN1 in-place
    k_glu<<<BB * HH * LL / 256, 256>>>(dt, du);
    k_ln<<<BB * LL / 256, 256>>>(du, ln1g, ln1b);
    // 7. S4 layer 2
    k_ssm<<<(BB * HH) / 4, 128>>>(du, dy, dz + HN, dct + HN, s2_D);
    k_gemm<<<dim3(LL / 64, H2 / 64, BB), 256>>>(s2_oW, dy, s2_ob, dt, H2, HH, nullptr);
    k_glu<<<BB * HH * LL / 256, 256>>>(dt, du);
    k_ln<<<BB * LL / 256, 256>>>(du, ln2g, ln2b);
    // 8. gate/filter activation -> z [B,C,L]
    k_act<<<BB * CC * LL / 256, 256>>>(du, dy);
    // 9. output projection: t = out_W @ z + out_b  [B,2C,L]
    k_gemm<<<dim3(LL / 64, HH / 64, BB), 256>>>(outW, dy, outb, dt, HH, CC, nullptr);
    // 10. residual/skip split into d_out
    k_final<<<BB * CC * LL / 256, 256>>>(dt, x, out);
}

// round 3
// speedup vs baseline: 1.3149x; 1.3149x over previous
#include <cuda_runtime.h>
#include <math.h>
#include <stdint.h>

#define BB 16
#define CC 256
#define LL 2048
#define EE 512
#define NN 64
#define HH 512
#define H2 1024

// ---------------- scratch ----------------
__device__ float  g_d[BB * CC];                 // diffusion projection [B,C]
__device__ float  g_e[BB * HH];                 // fused per-batch bias: in_W@d + in_b
__device__ float2 g_z [2 * HH * NN];
__device__ float2 g_ct[2 * HH * NN];
__device__ float  g_u[BB * HH * LL];
__device__ float  g_y[BB * HH * LL];
__device__ float  g_t[(size_t)BB * H2 * LL];

// ---------------- math helpers ----------------
__device__ __forceinline__ float sigf(float x) {
    return __fdividef(1.f, 1.f + __expf(-x));
}
__device__ __forceinline__ float tanh_fast(float x) {
    return fmaf(2.f, __fdividef(1.f, 1.f + __expf(-2.f * x)), -1.f);
}
__device__ __forceinline__ float geluf(float x) {
    // tanh-approx GELU via sigmoid identity: 0.5*(1+tanh(z)) = sigmoid(2z)
    float t = x * fmaf(0.044715f, x * x, 1.f);
    return x * sigf(1.5957691216057308f * t);
}

// ---------------- diffusion projection d[b,c] ----------------
__global__ void k_dproj(const float* __restrict__ demb, const float* __restrict__ W,
                        const float* __restrict__ bias, float* __restrict__ d) {
    int b = blockIdx.x;
    int c = threadIdx.x;  // 256
    __shared__ float se[EE];
    for (int e = threadIdx.x; e < EE; e += 256) se[e] = demb[b * EE + e];
    __syncthreads();
    float acc = 0.f;
#pragma unroll 8
    for (int e = 0; e < EE; e++) acc = fmaf(se[e], W[c * EE + e], acc);
    d[b * CC + c] = acc + bias[c];
}

// ---------------- fused input bias: e[b,o] = sum_k in_W[o,k]*d[b,k] + in_b[o] ----------------
__global__ void k_ebias(const float* __restrict__ W, const float* __restrict__ d,
                        const float* __restrict__ bias, float* __restrict__ e) {
    int b = blockIdx.x;
    int o = blockIdx.y * 128 + threadIdx.x;
    __shared__ float sd[CC];
    for (int k = threadIdx.x; k < CC; k += 128) sd[k] = d[b * CC + k];
    __syncthreads();
    float acc = 0.f;
#pragma unroll 8
    for (int k = 0; k < CC; k++) acc = fmaf(W[(size_t)o * CC + k], sd[k], acc);
    e[b * HH + o] = acc + bias[o];
}

// ---------------- SSM precompute ----------------
__global__ void k_prec(const float* __restrict__ log_dt, const float* __restrict__ Are,
                       const float* __restrict__ Aim, const float* __restrict__ Cre,
                       const float* __restrict__ Cim, float2* __restrict__ z,
                       float2* __restrict__ ct) {
    int i = blockIdx.x * blockDim.x + threadIdx.x;
    if (i >= HH * NN) return;
    int h = i / NN;
    float dt = expf(log_dt[h]);
    float A_r = Are[i], A_i = Aim[i];
    float ar = A_r * dt, ai = A_i * dt;
    float er = expf(ar);
    float s, c0;
    sincosf(ai, &s, &c0);
    float zr = er * c0, zi = er * s;
    float wr = zr - 1.f, wi = zi;
    float den = A_r * A_r + A_i * A_i;
    float inv = 1.f / den;
    float qr = (wr * A_r + wi * A_i) * inv;
    float qi = (wi * A_r - wr * A_i) * inv;
    float cr = Cre[i], ci = Cim[i];
    ct[i] = make_float2(2.f * (cr * qr - ci * qi), 2.f * (cr * qi + ci * qr));
    z[i] = make_float2(zr, zi);
}

// ---------------- diagonal SSM recurrence + D-skip + GELU ----------------
// One warp per (b,h); 64 complex states = 2 per lane; butterfly reduce.
__global__ void k_ssm(const float* __restrict__ in, float* __restrict__ out,
                      const float2* __restrict__ zarr, const float2* __restrict__ ctarr,
                      const float* __restrict__ Dv) {
    int w = (blockIdx.x * blockDim.x + threadIdx.x) >> 5;
    int lane = threadIdx.x & 31;
    int b = w >> 9, h = w & (HH - 1);
    float2 z0 = zarr[h * NN + lane];
    float2 z1 = zarr[h * NN + 32 + lane];
    float2 c0 = ctarr[h * NN + lane];
    float2 c1 = ctarr[h * NN + 32 + lane];
    float Dh = Dv[h];
    const float4* ip = (const float4*)(in + (size_t)(b * HH + h) * LL);
    float4* op = (float4*)(out + (size_t)(b * HH + h) * LL);
    float s0r = 0.f, s0i = 0.f, s1r = 0.f, s1i = 0.f;
    for (int l4 = 0; l4 < LL / 4; l4++) {
        float4 u4 = __ldg(ip + l4);
        float o[4];
#pragma unroll
        for (int j = 0; j < 4; j++) {
            float u = (j == 0) ? u4.x : (j == 1) ? u4.y : (j == 2) ? u4.z : u4.w;
            float sr = s0r, si = s0i;
            s0r = fmaf(z0.x, sr, fmaf(-z0.y, si, u));
            s0i = fmaf(z0.x, si, z0.y * sr);
            sr = s1r; si = s1i;
            s1r = fmaf(z1.x, sr, fmaf(-z1.y, si, u));
            s1i = fmaf(z1.x, si, z1.y * sr);
            float p = c0.x * s0r;
            p = fmaf(-c0.y, s0i, p);
            p = fmaf(c1.x, s1r, p);
            p = fmaf(-c1.y, s1i, p);
#pragma unroll
            for (int off = 16; off; off >>= 1) p += __shfl_xor_sync(0xffffffffu, p, off);
            o[j] = fmaf(Dh, u, p);
        }
        if (lane == 0) {
            float4 r;
            r.x = geluf(o[0]); r.y = geluf(o[1]);
            r.z = geluf(o[2]); r.w = geluf(o[3]);
            op[l4] = r;
        }
    }
}

// ---------------- 128x128 tiled fp32 GEMM, cp.async double-buffered ----------------
// Y[b,o,l] = sum_k W[o,k] * X[b,k,l] + bias
#define TO 128
#define TL 128
#define TK 16

__device__ __forceinline__ void cp16(uint32_t dst, const void* src) {
    asm volatile("cp.async.ca.shared.global [%0], [%1], 16;\n" :: "r"(dst), "l"(src));
}

__global__ __launch_bounds__(256, 2)
void k_gemm(const float* __restrict__ W, const float* __restrict__ X,
            const float* __restrict__ bias, int bias_per_batch,
            float* __restrict__ Y, int O, int K,
            const float* __restrict__ xres, int final_mode) {
    __shared__ __align__(16) float sA[2][TK][TO + 4];
    __shared__ __align__(16) float sB[2][TK][TL + 4];
    int t = threadIdx.x;
    int tx = t & 15, ty = t >> 4;
    int o0 = blockIdx.y * TO, l0 = blockIdx.x * TL;
    int b = blockIdx.z;
    const float* Xb = X + (size_t)b * K * LL;
    int nk = K / TK;

    // A-load mapping: 2 float4 per thread
    int aO[2], aK[2];
    aO[0] = t >> 2;         aK[0] = t & 3;
    aO[1] = (t + 256) >> 2; aK[1] = (t + 256) & 3;
    // B cp.async mapping
    int brow = t >> 4, bc = t & 15;

    float4 aP[2];
    float acc[8][8];
#pragma unroll
    for (int i = 0; i < 8; i++)
#pragma unroll
        for (int j = 0; j < 8; j++) acc[i][j] = 0.f;

    // prologue
    {
#pragma unroll
        for (int r = 0; r < 2; r++)
            aP[r] = *(const float4*)&W[(size_t)(o0 + aO[r]) * K + aK[r] * 4];
        uint32_t d0 = (uint32_t)__cvta_generic_to_shared(&sB[0][brow][bc * 8]);
        const float* s0 = Xb + (size_t)brow * LL + l0 + bc * 8;
        cp16(d0, s0);
        cp16(d0 + 16, s0 + 4);
        asm volatile("cp.async.commit_group;\n");
#pragma unroll
        for (int r = 0; r < 2; r++) {
            sA[0][aK[r] * 4 + 0][aO[r]] = aP[r].x;
            sA[0][aK[r] * 4 + 1][aO[r]] = aP[r].y;
            sA[0][aK[r] * 4 + 2][aO[r]] = aP[r].z;
            sA[0][aK[r] * 4 + 3][aO[r]] = aP[r].w;
        }
        asm volatile("cp.async.wait_group 0;\n");
        __syncthreads();
    }

    for (int kc = 0; kc < nk; kc++) {
        int cur = kc & 1, nxt = cur ^ 1;
        bool more = (kc + 1) < nk;
        if (more) {
            int kb = (kc + 1) * TK;
#pragma unroll
            for (int r = 0; r < 2; r++)
                aP[r] = *(const float4*)&W[(size_t)(o0 + aO[r]) * K + kb + aK[r] * 4];
            uint32_t d0 = (uint32_t)__cvta_generic_to_shared(&sB[nxt][brow][bc * 8]);
            const float* s0 = Xb + (size_t)(kb + brow) * LL + l0 + bc * 8;
            cp16(d0, s0);
            cp16(d0 + 16, s0 + 4);
            asm volatile("cp.async.commit_group;\n");
        }
#pragma unroll
        for (int k = 0; k < TK; k++) {
            float4 a0 = *(const float4*)&sA[cur][k][ty * 8];
            float4 a1 = *(const float4*)&sA[cur][k][ty * 8 + 4];
            float4 b0 = *(const float4*)&sB[cur][k][tx * 8];
            float4 b1 = *(const float4*)&sB[cur][k][tx * 8 + 4];
            float av[8] = {a0.x, a0.y, a0.z, a0.w, a1.x, a1.y, a1.z, a1.w};
            float bv[8] = {b0.x, b0.y, b0.z, b0.w, b1.x, b1.y, b1.z, b1.w};
#pragma unroll
            for (int i = 0; i < 8; i++)
#pragma unroll
                for (int j = 0; j < 8; j++) acc[i][j] = fmaf(av[i], bv[j], acc[i][j]);
        }
        if (more) {
#pragma unroll
            for (int r = 0; r < 2; r++) {
                sA[nxt][aK[r] * 4 + 0][aO[r]] = aP[r].x;
                sA[nxt][aK[r] * 4 + 1][aO[r]] = aP[r].y;
                sA[nxt][aK[r] * 4 + 2][aO[r]] = aP[r].z;
                sA[nxt][aK[r] * 4 + 3][aO[r]] = aP[r].w;
            }
            asm volatile("cp.async.wait_group 0;\n");
        }
        __syncthreads();
    }

    // epilogue
#pragma unroll
    for (int i = 0; i < 8; i++) {
        int o = o0 + ty * 8 + i;
        float bi = bias_per_batch ? bias[b * O + o] : bias[o];
        float v[8];
#pragma unroll
        for (int j = 0; j < 8; j++) v[j] = acc[i][j] + bi;
        int l = l0 + tx * 8;
        if (!final_mode) {
            float* yp = Y + (size_t)b * O * LL + (size_t)o * LL + l;
            *(float4*)yp = make_float4(v[0], v[1], v[2], v[3]);
            *(float4*)(yp + 4) = make_float4(v[4], v[5], v[6], v[7]);
        } else {
            if (o < CC) {
                size_t idx = (size_t)(b * CC + o) * LL + l;
                float4 x0 = *(const float4*)(xres + idx);
                float4 x1 = *(const float4*)(xres + idx + 4);
                const float s = 0.70710678118654752f;
                *(float4*)(Y + idx) = make_float4((x0.x + v[0]) * s, (x0.y + v[1]) * s,
                                                  (x0.z + v[2]) * s, (x0.w + v[3]) * s);
                *(float4*)(Y + idx + 4) = make_float4((x1.x + v[4]) * s, (x1.y + v[5]) * s,
                                                      (x1.z + v[6]) * s, (x1.w + v[7]) * s);
            } else {
                size_t idx = (size_t)BB * CC * LL + (size_t)(b * CC + (o - CC)) * LL + l;
                *(float4*)(Y + idx) = make_float4(v[0], v[1], v[2], v[3]);
                *(float4*)(Y + idx + 4) = make_float4(v[4], v[5], v[6], v[7]);
            }
        }
    }
}

// ---------------- GLU ----------------
__global__ void k_glu(const float* __restrict__ t, float* __restrict__ u) {
    int i = blockIdx.x * 256 + threadIdx.x;
    int b = i / (HH * LL);
    int r = i - b * HH * LL;
    const float* tb = t + (size_t)b * H2 * LL;
    float a = tb[r];
    float g = tb[r + HH * LL];
    u[i] = a * sigf(g);
}

// ---------------- LayerNorm over channels ----------------
__global__ void k_ln(float* __restrict__ u, const float* __restrict__ g,
                     const float* __restrict__ be) {
    int i = blockIdx.x * blockDim.x + threadIdx.x;
    int b = i / LL, l = i - b * LL;
    float* base = u + (size_t)b * HH * LL + l;
    float sum = 0.f, ss = 0.f;
#pragma unroll 8
    for (int h = 0; h < HH; h++) {
        float v = base[(size_t)h * LL];
        sum += v;
        ss = fmaf(v, v, ss);
    }
    float mu = sum * (1.f / HH);
    float var = ss * (1.f / HH) - mu * mu;
    float rs = rsqrtf(var + 1e-5f);
#pragma unroll 8
    for (int h = 0; h < HH; h++) {
        float v = base[(size_t)h * LL];
        base[(size_t)h * LL] = (v - mu) * rs * __ldg(g + h) + __ldg(be + h);
    }
}

// ---------------- gate/filter activation ----------------
__global__ void k_act(const float* __restrict__ u, float* __restrict__ zout) {
    int i = blockIdx.x * 256 + threadIdx.x;
    int b = i / (CC * LL);
    int r = i - b * CC * LL;
    const float* ub = u + (size_t)b * HH * LL;
    float gt = ub[r];
    float fl = ub[r + CC * LL];
    zout[i] = sigf(gt) * tanh_fast(fl);
}

// ---------------- launch ----------------
extern "C" void kernel_launch(void* const* d_in, const int* in_sizes, int n_in,
                              void* d_out, int out_size) {
    const float* x    = (const float*)d_in[0];
    const float* demb = (const float*)d_in[1];
    const float* dpW  = (const float*)d_in[2];
    const float* dpb  = (const float*)d_in[3];
    const float* inW  = (const float*)d_in[4];
    const float* inb  = (const float*)d_in[5];
    const float* outW = (const float*)d_in[6];
    const float* outb = (const float*)d_in[7];
    const float* ln1g = (const float*)d_in[8];
    const float* ln1b = (const float*)d_in[9];
    const float* ln2g = (const float*)d_in[10];
    const float* ln2b = (const float*)d_in[11];
    const float* s1_logdt = (const float*)d_in[12];
    const float* s1_Are   = (const float*)d_in[13];
    const float* s1_Aim   = (const float*)d_in[14];
    const float* s1_Cre   = (const float*)d_in[15];
    const float* s1_Cim   = (const float*)d_in[16];
    const float* s1_D     = (const float*)d_in[17];
    const float* s1_oW    = (const float*)d_in[18];
    const float* s1_ob    = (const float*)d_in[19];
    const float* s2_logdt = (const float*)d_in[20];
    const float* s2_Are   = (const float*)d_in[21];
    const float* s2_Aim   = (const float*)d_in[22];
    const float* s2_Cre   = (const float*)d_in[23];
    const float* s2_Cim   = (const float*)d_in[24];
    const float* s2_D     = (const float*)d_in[25];
    const float* s2_oW    = (const float*)d_in[26];
    const float* s2_ob    = (const float*)d_in[27];

    float* out = (float*)d_out;

    float *du, *dy, *dt, *dd, *de;
    float2 *dz, *dct;
    cudaGetSymbolAddress((void**)&du, g_u);
    cudaGetSymbolAddress((void**)&dy, g_y);
    cudaGetSymbolAddress((void**)&dt, g_t);
    cudaGetSymbolAddress((void**)&dd, g_d);
    cudaGetSymbolAddress((void**)&de, g_e);
    cudaGetSymbolAddress((void**)&dz, g_z);
    cudaGetSymbolAddress((void**)&dct, g_ct);

    const int HN = HH * NN;

    k_dproj<<<BB, 256>>>(demb, dpW, dpb, dd);
    k_prec<<<(HN + 255) / 256, 256>>>(s1_logdt, s1_Are, s1_Aim, s1_Cre, s1_Cim, dz, dct);
    k_prec<<<(HN + 255) / 256, 256>>>(s2_logdt, s2_Are, s2_Aim, s2_Cre, s2_Cim, dz + HN, dct + HN);
    k_ebias<<<dim3(BB, HH / 128), 128>>>(inW, dd, inb, de);

    // in-proj: u = in_W @ x + e(b,:)   [B,H,L]
    k_gemm<<<dim3(LL / TL, HH / TO, BB), 256>>>(inW, x, de, 1, du, HH, CC, nullptr, 0);
    // S4 layer 1
    k_ssm<<<(BB * HH) / 4, 128>>>(du, dy, dz, dct, s1_D);
    k_gemm<<<dim3(LL / TL, H2 / TO, BB), 256>>>(s1_oW, dy, s1_ob, 0, dt, H2, HH, nullptr, 0);
    k_glu<<<BB * HH * LL / 256, 256>>>(dt, du);
    k_ln<<<BB * LL / 256, 256>>>(du, ln1g, ln1b);
    // S4 layer 2
    k_ssm<<<(BB * HH) / 4, 128>>>(du, dy, dz + HN, dct + HN, s2_D);
    k_gemm<<<dim3(LL / TL, H2 / TO, BB), 256>>>(s2_oW, dy, s2_ob, 0, dt, H2, HH, nullptr, 0);
    k_glu<<<BB * HH * LL / 256, 256>>>(dt, du);
    k_ln<<<BB * LL / 256, 256>>>(du, ln2g, ln2b);
    // gate/filter -> z [B,C,L]
    k_act<<<BB * CC * LL / 256, 256>>>(du, dy);
    // out-proj fused with residual/skip split, writes d_out
    k_gemm<<<dim3(LL / TL, HH / TO, BB), 256>>>(outW, dy, outb, 0, out, HH, CC, x, 1);
}

// round 4
// speedup vs baseline: 1.7890x; 1.3605x over previous
#include <cuda_runtime.h>
#include <cuda_bf16.h>
#include <math.h>
#include <stdint.h>

#define BB 16
#define CC 256
#define LL 2048
#define EE 512
#define NN 64
#define HH 512
#define H2 1024

// ---------------- scratch ----------------
__device__ float  g_d[BB * CC];
__device__ float  g_e[BB * HH];
__device__ float2 g_z [2 * HH * NN];
__device__ float2 g_ct[2 * HH * NN];
__device__ float  g_u[BB * HH * LL];
__device__ float  g_y[BB * HH * LL];
__device__ float  g_t[(size_t)BB * H2 * LL];

// ---------------- math helpers ----------------
__device__ __forceinline__ float sigf(float x) {
    return __fdividef(1.f, 1.f + __expf(-x));
}
__device__ __forceinline__ float tanh_fast(float x) {
    return fmaf(2.f, __fdividef(1.f, 1.f + __expf(-2.f * x)), -1.f);
}
__device__ __forceinline__ float geluf(float x) {
    float t = x * fmaf(0.044715f, x * x, 1.f);
    return x * sigf(1.5957691216057308f * t);
}

// ---------------- diffusion projection d[b,c] ----------------
__global__ void k_dproj(const float* __restrict__ demb, const float* __restrict__ W,
                        const float* __restrict__ bias, float* __restrict__ d) {
    int b = blockIdx.x;
    int c = threadIdx.x;
    __shared__ float se[EE];
    for (int e = threadIdx.x; e < EE; e += 256) se[e] = demb[b * EE + e];
    __syncthreads();
    float acc = 0.f;
#pragma unroll 8
    for (int e = 0; e < EE; e++) acc = fmaf(se[e], W[c * EE + e], acc);
    d[b * CC + c] = acc + bias[c];
}

// ---------------- fused input bias: e[b,o] ----------------
__global__ void k_ebias(const float* __restrict__ W, const float* __restrict__ d,
                        const float* __restrict__ bias, float* __restrict__ e) {
    int b = blockIdx.x;
    int o = blockIdx.y * 128 + threadIdx.x;
    __shared__ float sd[CC];
    for (int k = threadIdx.x; k < CC; k += 128) sd[k] = d[b * CC + k];
    __syncthreads();
    float acc = 0.f;
#pragma unroll 8
    for (int k = 0; k < CC; k++) acc = fmaf(W[(size_t)o * CC + k], sd[k], acc);
    e[b * HH + o] = acc + bias[o];
}

// ---------------- SSM precompute ----------------
__global__ void k_prec(const float* __restrict__ log_dt, const float* __restrict__ Are,
                       const float* __restrict__ Aim, const float* __restrict__ Cre,
                       const float* __restrict__ Cim, float2* __restrict__ z,
                       float2* __restrict__ ct) {
    int i = blockIdx.x * blockDim.x + threadIdx.x;
    if (i >= HH * NN) return;
    int h = i / NN;
    float dt = expf(log_dt[h]);
    float A_r = Are[i], A_i = Aim[i];
    float ar = A_r * dt, ai = A_i * dt;
    float er = expf(ar);
    float s, c0;
    sincosf(ai, &s, &c0);
    float zr = er * c0, zi = er * s;
    float wr = zr - 1.f, wi = zi;
    float den = A_r * A_r + A_i * A_i;
    float inv = 1.f / den;
    float qr = (wr * A_r + wi * A_i) * inv;
    float qi = (wi * A_r - wr * A_i) * inv;
    float cr = Cre[i], ci = Cim[i];
    ct[i] = make_float2(2.f * (cr * qr - ci * qi), 2.f * (cr * qi + ci * qr));
    z[i] = make_float2(zr, zi);
}

// ---------------- diagonal SSM recurrence + D-skip + GELU ----------------
__global__ void k_ssm(const float* __restrict__ in, float* __restrict__ out,
                      const float2* __restrict__ zarr, const float2* __restrict__ ctarr,
                      const float* __restrict__ Dv) {
    int w = (blockIdx.x * blockDim.x + threadIdx.x) >> 5;
    int lane = threadIdx.x & 31;
    int b = w >> 9, h = w & (HH - 1);
    float2 z0 = zarr[h * NN + lane];
    float2 z1 = zarr[h * NN + 32 + lane];
    float2 c0 = ctarr[h * NN + lane];
    float2 c1 = ctarr[h * NN + 32 + lane];
    float Dh = Dv[h];
    const float4* ip = (const float4*)(in + (size_t)(b * HH + h) * LL);
    float4* op = (float4*)(out + (size_t)(b * HH + h) * LL);
    float s0r = 0.f, s0i = 0.f, s1r = 0.f, s1i = 0.f;
    for (int l4 = 0; l4 < LL / 4; l4++) {
        float4 u4 = __ldg(ip + l4);
        float o[4];
#pragma unroll
        for (int j = 0; j < 4; j++) {
            float u = (j == 0) ? u4.x : (j == 1) ? u4.y : (j == 2) ? u4.z : u4.w;
            float sr = s0r, si = s0i;
            s0r = fmaf(z0.x, sr, fmaf(-z0.y, si, u));
            s0i = fmaf(z0.x, si, z0.y * sr);
            sr = s1r; si = s1i;
            s1r = fmaf(z1.x, sr, fmaf(-z1.y, si, u));
            s1i = fmaf(z1.x, si, z1.y * sr);
            float p = c0.x * s0r;
            p = fmaf(-c0.y, s0i, p);
            p = fmaf(c1.x, s1r, p);
            p = fmaf(-c1.y, s1i, p);
#pragma unroll
            for (int off = 16; off; off >>= 1) p += __shfl_xor_sync(0xffffffffu, p, off);
            o[j] = fmaf(Dh, u, p);
        }
        if (lane == 0) {
            float4 r;
            r.x = geluf(o[0]); r.y = geluf(o[1]);
            r.z = geluf(o[2]); r.w = geluf(o[3]);
            op[l4] = r;
        }
    }
}

// ======================================================================
// bf16x3 split-precision tensor-core GEMM
// Y[b,o,l] = sum_k W[o,k]*X[b,k,l] + bias;  D = Ahi*Bhi + Ahi*Blo + Alo*Bhi
// Block tile 128(O) x 128(L), K-chunk 16; 8 warps = 2(O) x 4(L); warp 64x32.
// ======================================================================
#define SA_STRIDE 24     /* bf16 units per A row (16 + 8 pad) */
#define SB_STRIDE 136    /* bf16 units per B row (128 + 8 pad) */

__device__ __forceinline__ void ldsm_x4(uint32_t& r0, uint32_t& r1, uint32_t& r2,
                                        uint32_t& r3, uint32_t addr) {
    asm volatile("ldmatrix.sync.aligned.m8n8.x4.shared.b16 {%0,%1,%2,%3}, [%4];"
                 : "=r"(r0), "=r"(r1), "=r"(r2), "=r"(r3) : "r"(addr));
}
__device__ __forceinline__ void ldsm_x2t(uint32_t& r0, uint32_t& r1, uint32_t addr) {
    asm volatile("ldmatrix.sync.aligned.m8n8.x2.trans.shared.b16 {%0,%1}, [%2];"
                 : "=r"(r0), "=r"(r1) : "r"(addr));
}
__device__ __forceinline__ void mma16816(float* c, const uint32_t* a, const uint32_t* b) {
    asm volatile("mma.sync.aligned.m16n8k16.row.col.f32.bf16.bf16.f32 "
                 "{%0,%1,%2,%3}, {%4,%5,%6,%7}, {%8,%9}, {%0,%1,%2,%3};"
                 : "+f"(c[0]), "+f"(c[1]), "+f"(c[2]), "+f"(c[3])
                 : "r"(a[0]), "r"(a[1]), "r"(a[2]), "r"(a[3]), "r"(b[0]), "r"(b[1]));
}
__device__ __forceinline__ uint32_t pack_bf16(__nv_bfloat16 a, __nv_bfloat16 b) {
    __nv_bfloat162 v(a, b);
    return *(uint32_t*)&v;
}

__global__ __launch_bounds__(256)
void k_gemm(const float* __restrict__ W, const float* __restrict__ X,
            const float* __restrict__ bias, int bias_per_batch,
            float* __restrict__ Y, int O, int K,
            const float* __restrict__ xres, int final_mode) {
    __shared__ __align__(16) __nv_bfloat16 sAh[128 * SA_STRIDE];
    __shared__ __align__(16) __nv_bfloat16 sAl[128 * SA_STRIDE];
    __shared__ __align__(16) __nv_bfloat16 sBh[16 * SB_STRIDE];
    __shared__ __align__(16) __nv_bfloat16 sBl[16 * SB_STRIDE];

    int t = threadIdx.x;
    int lane = t & 31, warp = t >> 5;
    int wo = warp >> 2, wl = warp & 3;       // warp tile: rows wo*64, cols wl*32
    int o0 = blockIdx.y * 128, l0 = blockIdx.x * 128;
    int b = blockIdx.z;
    const float* Xb = X + (size_t)b * K * LL;
    int nk = K / 16;

    // staging maps
    int ar = t >> 1, ah = t & 1;             // A: row ar (0..127), k-half ah (8 floats)
    int br = t >> 4, bc = (t & 15) * 8;      // B: k-row br (0..15), col bc (8 floats)

    float acc[4][4][4];
#pragma unroll
    for (int i = 0; i < 4; i++)
#pragma unroll
        for (int j = 0; j < 4; j++)
#pragma unroll
            for (int q = 0; q < 4; q++) acc[i][j][q] = 0.f;

    float4 pa0, pa1, pb0, pb1;
    // prologue loads (chunk 0)
    {
        const float* wp = W + (size_t)(o0 + ar) * K + ah * 8;
        pa0 = *(const float4*)wp;
        pa1 = *(const float4*)(wp + 4);
        const float* xp = Xb + (size_t)br * LL + l0 + bc;
        pb0 = *(const float4*)xp;
        pb1 = *(const float4*)(xp + 4);
    }

    // ldmatrix addresses (per lane)
    uint32_t aAddrBase = (uint32_t)__cvta_generic_to_shared(sAh);
    uint32_t aAddrBaseL = (uint32_t)__cvta_generic_to_shared(sAl);
    uint32_t bAddrBase = (uint32_t)__cvta_generic_to_shared(sBh);
    uint32_t bAddrBaseL = (uint32_t)__cvta_generic_to_shared(sBl);
    int aRow = wo * 64 + (lane & 15);        // + mi*16
    int aCol = (lane >> 4) * 8;
    uint32_t aOff = (uint32_t)((aRow * SA_STRIDE + aCol) * 2);
    uint32_t bOff = (uint32_t)(((lane & 15) * SB_STRIDE + wl * 32) * 2);  // + ni*8*2

    for (int kc = 0; kc < nk; kc++) {
        // ---- stage prefetched regs -> smem (hi/lo split) ----
        {
            float av[8] = {pa0.x, pa0.y, pa0.z, pa0.w, pa1.x, pa1.y, pa1.z, pa1.w};
            int base = ar * SA_STRIDE + ah * 8;
#pragma unroll
            for (int j = 0; j < 8; j += 2) {
                __nv_bfloat16 h0 = __float2bfloat16(av[j]);
                __nv_bfloat16 h1 = __float2bfloat16(av[j + 1]);
                __nv_bfloat16 q0 = __float2bfloat16(av[j] - __bfloat162float(h0));
                __nv_bfloat16 q1 = __float2bfloat16(av[j + 1] - __bfloat162float(h1));
                *(uint32_t*)&sAh[base + j] = pack_bf16(h0, h1);
                *(uint32_t*)&sAl[base + j] = pack_bf16(q0, q1);
            }
            float bv[8] = {pb0.x, pb0.y, pb0.z, pb0.w, pb1.x, pb1.y, pb1.z, pb1.w};
            int bbase = br * SB_STRIDE + bc;
#pragma unroll
            for (int j = 0; j < 8; j += 2) {
                __nv_bfloat16 h0 = __float2bfloat16(bv[j]);
                __nv_bfloat16 h1 = __float2bfloat16(bv[j + 1]);
                __nv_bfloat16 q0 = __float2bfloat16(bv[j] - __bfloat162float(h0));
                __nv_bfloat16 q1 = __float2bfloat16(bv[j + 1] - __bfloat162float(h1));
                *(uint32_t*)&sBh[bbase + j] = pack_bf16(h0, h1);
                *(uint32_t*)&sBl[bbase + j] = pack_bf16(q0, q1);
            }
        }
        __syncthreads();

        // ---- prefetch next chunk ----
        if (kc + 1 < nk) {
            int kb = (kc + 1) * 16;
            const float* wp = W + (size_t)(o0 + ar) * K + kb + ah * 8;
            pa0 = *(const float4*)wp;
            pa1 = *(const float4*)(wp + 4);
            const float* xp = Xb + (size_t)(kb + br) * LL + l0 + bc;
            pb0 = *(const float4*)xp;
            pb1 = *(const float4*)(xp + 4);
        }

        // ---- load fragments ----
        uint32_t aH[4][4], aL[4][4], bH[4][2], bL[4][2];
#pragma unroll
        for (int mi = 0; mi < 4; mi++) {
            uint32_t off = aOff + (uint32_t)(mi * 16 * SA_STRIDE * 2);
            ldsm_x4(aH[mi][0], aH[mi][1], aH[mi][2], aH[mi][3], aAddrBase + off);
            ldsm_x4(aL[mi][0], aL[mi][1], aL[mi][2], aL[mi][3], aAddrBaseL + off);
        }
#pragma unroll
        for (int ni = 0; ni < 4; ni++) {
            uint32_t off = bOff + (uint32_t)(ni * 8 * 2);
            ldsm_x2t(bH[ni][0], bH[ni][1], bAddrBase + off);
            ldsm_x2t(bL[ni][0], bL[ni][1], bAddrBaseL + off);
        }

        // ---- 3-term MMAs ----
#pragma unroll
        for (int mi = 0; mi < 4; mi++)
#pragma unroll
            for (int ni = 0; ni < 4; ni++) {
                mma16816(acc[mi][ni], aH[mi], bH[ni]);
                mma16816(acc[mi][ni], aH[mi], bL[ni]);
                mma16816(acc[mi][ni], aL[mi], bH[ni]);
            }
        __syncthreads();
    }

    // ---- epilogue ----
    int g = lane >> 2, t4 = lane & 3;
#pragma unroll
    for (int mi = 0; mi < 4; mi++) {
#pragma unroll
        for (int ni = 0; ni < 4; ni++) {
            int row0 = o0 + wo * 64 + mi * 16 + g;
            int row1 = row0 + 8;
            int col = l0 + wl * 32 + ni * 8 + t4 * 2;
            float b0 = bias_per_batch ? bias[b * O + row0] : bias[row0];
            float b1 = bias_per_batch ? bias[b * O + row1] : bias[row1];
            float v00 = acc[mi][ni][0] + b0, v01 = acc[mi][ni][1] + b0;
            float v10 = acc[mi][ni][2] + b1, v11 = acc[mi][ni][3] + b1;
            if (!final_mode) {
                float* y0 = Y + (size_t)b * O * LL + (size_t)row0 * LL + col;
                float* y1 = Y + (size_t)b * O * LL + (size_t)row1 * LL + col;
                *(float2*)y0 = make_float2(v00, v01);
                *(float2*)y1 = make_float2(v10, v11);
            } else {
                const float s = 0.70710678118654752f;
                // row0
                {
                    int o = row0;
                    if (o < CC) {
                        size_t idx = (size_t)(b * CC + o) * LL + col;
                        float2 xv = *(const float2*)(xres + idx);
                        *(float2*)(Y + idx) = make_float2((xv.x + v00) * s, (xv.y + v01) * s);
                    } else {
                        size_t idx = (size_t)BB * CC * LL + (size_t)(b * CC + (o - CC)) * LL + col;
                        *(float2*)(Y + idx) = make_float2(v00, v01);
                    }
                }
                // row1
                {
                    int o = row1;
                    if (o < CC) {
                        size_t idx = (size_t)(b * CC + o) * LL + col;
                        float2 xv = *(const float2*)(xres + idx);
                        *(float2*)(Y + idx) = make_float2((xv.x + v10) * s, (xv.y + v11) * s);
                    } else {
                        size_t idx = (size_t)BB * CC * LL + (size_t)(b * CC + (o - CC)) * LL + col;
                        *(float2*)(Y + idx) = make_float2(v10, v11);
                    }
                }
            }
        }
    }
}

// ---------------- GLU ----------------
__global__ void k_glu(const float* __restrict__ t, float* __restrict__ u) {
    int i = blockIdx.x * 256 + threadIdx.x;
    int b = i / (HH * LL);
    int r = i - b * HH * LL;
    const float* tb = t + (size_t)b * H2 * LL;
    float a = tb[r];
    float g = tb[r + HH * LL];
    u[i] = a * sigf(g);
}

// ---------------- LayerNorm over channels ----------------
__global__ void k_ln(float* __restrict__ u, const float* __restrict__ g,
                     const float* __restrict__ be) {
    int i = blockIdx.x * blockDim.x + threadIdx.x;
    int b = i / LL, l = i - b * LL;
    float* base = u + (size_t)b * HH * LL + l;
    float sum = 0.f, ss = 0.f;
#pragma unroll 8
    for (int h = 0; h < HH; h++) {
        float v = base[(size_t)h * LL];
        sum += v;
        ss = fmaf(v, v, ss);
    }
    float mu = sum * (1.f / HH);
    float var = ss * (1.f / HH) - mu * mu;
    float rs = rsqrtf(var + 1e-5f);
#pragma unroll 8
    for (int h = 0; h < HH; h++) {
        float v = base[(size_t)h * LL];
        base[(size_t)h * LL] = (v - mu) * rs * __ldg(g + h) + __ldg(be + h);
    }
}

// ---------------- gate/filter activation ----------------
__global__ void k_act(const float* __restrict__ u, float* __restrict__ zout) {
    int i = blockIdx.x * 256 + threadIdx.x;
    int b = i / (CC * LL);
    int r = i - b * CC * LL;
    const float* ub = u + (size_t)b * HH * LL;
    float gt = ub[r];
    float fl = ub[r + CC * LL];
    zout[i] = sigf(gt) * tanh_fast(fl);
}

// ---------------- launch ----------------
extern "C" void kernel_launch(void* const* d_in, const int* in_sizes, int n_in,
                              void* d_out, int out_size) {
    const float* x    = (const float*)d_in[0];
    const float* demb = (const float*)d_in[1];
    const float* dpW  = (const float*)d_in[2];
    const float* dpb  = (const float*)d_in[3];
    const float* inW  = (const float*)d_in[4];
    const float* inb  = (const float*)d_in[5];
    const float* outW = (const float*)d_in[6];
    const float* outb = (const float*)d_in[7];
    const float* ln1g = (const float*)d_in[8];
    const float* ln1b = (const float*)d_in[9];
    const float* ln2g = (const float*)d_in[10];
    const float* ln2b = (const float*)d_in[11];
    const float* s1_logdt = (const float*)d_in[12];
    const float* s1_Are   = (const float*)d_in[13];
    const float* s1_Aim   = (const float*)d_in[14];
    const float* s1_Cre   = (const float*)d_in[15];
    const float* s1_Cim   = (const float*)d_in[16];
    const float* s1_D     = (const float*)d_in[17];
    const float* s1_oW    = (const float*)d_in[18];
    const float* s1_ob    = (const float*)d_in[19];
    const float* s2_logdt = (const float*)d_in[20];
    const float* s2_Are   = (const float*)d_in[21];
    const float* s2_Aim   = (const float*)d_in[22];
    const float* s2_Cre   = (const float*)d_in[23];
    const float* s2_Cim   = (const float*)d_in[24];
    const float* s2_D     = (const float*)d_in[25];
    const float* s2_oW    = (const float*)d_in[26];
    const float* s2_ob    = (const float*)d_in[27];

    float* out = (float*)d_out;

    float *du, *dy, *dt, *dd, *de;
    float2 *dz, *dct;
    cudaGetSymbolAddress((void**)&du, g_u);
    cudaGetSymbolAddress((void**)&dy, g_y);
    cudaGetSymbolAddress((void**)&dt, g_t);
    cudaGetSymbolAddress((void**)&dd, g_d);
    cudaGetSymbolAddress((void**)&de, g_e);
    cudaGetSymbolAddress((void**)&dz, g_z);
    cudaGetSymbolAddress((void**)&dct, g_ct);

    const int HN = HH * NN;

    k_dproj<<<BB, 256>>>(demb, dpW, dpb, dd);                       // 1
    k_ebias<<<dim3(BB, HH / 128), 128>>>(inW, dd, inb, de);         // 2
    k_prec<<<(HN + 255) / 256, 256>>>(s1_logdt, s1_Are, s1_Aim, s1_Cre, s1_Cim, dz, dct);  // 3
    // 4: profiled slot — in-proj GEMM
    k_gemm<<<dim3(LL / 128, HH / 128, BB), 256>>>(inW, x, de, 1, du, HH, CC, nullptr, 0);
    k_prec<<<(HN + 255) / 256, 256>>>(s2_logdt, s2_Are, s2_Aim, s2_Cre, s2_Cim, dz + HN, dct + HN);  // 5
    // S4 layer 1
    k_ssm<<<(BB * HH) / 4, 128>>>(du, dy, dz, dct, s1_D);
    k_gemm<<<dim3(LL / 128, H2 / 128, BB), 256>>>(s1_oW, dy, s1_ob, 0, dt, H2, HH, nullptr, 0);
    k_glu<<<BB * HH * LL / 256, 256>>>(dt, du);
    k_ln<<<BB * LL / 256, 256>>>(du, ln1g, ln1b);
    // S4 layer 2
    k_ssm<<<(BB * HH) / 4, 128>>>(du, dy, dz + HN, dct + HN, s2_D);
    k_gemm<<<dim3(LL / 128, H2 / 128, BB), 256>>>(s2_oW, dy, s2_ob, 0, dt, H2, HH, nullptr, 0);
    k_glu<<<BB * HH * LL / 256, 256>>>(dt, du);
    k_ln<<<BB * LL / 256, 256>>>(du, ln2g, ln2b);
    // gate/filter -> z
    k_act<<<BB * CC * LL / 256, 256>>>(du, dy);
    // out-proj fused with residual/skip split
    k_gemm<<<dim3(LL / 128, HH / 128, BB), 256>>>(outW, dy, outb, 0, out, HH, CC, x, 1);
}